// round 8
// baseline (speedup 1.0000x reference)
#include <cuda_runtime.h>
#include <cuda_bf16.h>
#include <math.h>
#include <stdint.h>

// ---------------- problem constants ----------------
#define NQ   32768
#define NE   262144
#define S    32768

typedef __nv_bfloat16 bf16;

// ---------------- scratch (device globals) ----------------
__device__ __align__(16) bf16  g_WcT [384 * 192];         // (proj_w @ msg0_w_top)^T [n][k]
__device__ __align__(16) bf16  g_WbT [384 * 192];         // msg0_w_bot^T
__device__ __align__(16) bf16  g_Wt1 [384 * 384];         // msg1_w^T
__device__ __align__(16) bf16  g_Wt2 [192 * 384];         // msg2_w^T
__device__ __align__(16) bf16  g_Wp0T[192 * 192];         // pred0_w^T
__device__ __align__(16) float g_bc[384];                 // folded bias
__device__ __align__(16) bf16  g_Xh [S * 192];            // x in bf16
__device__ __align__(16) bf16  g_QEh[NQ * 192];           // sincos embed bf16
__device__ __align__(16) float g_A1[S * 384];             // x @ Wc + bc (fp32)
__device__ __align__(16) float g_A2[NQ * 384];            // QE @ msg0_w_bot (fp32)
__device__ __align__(16) bf16  g_H2h[(size_t)NE * 192];   // msg2 output (bf16)
__device__ __align__(16) bf16  g_Mh [NQ * 192];           // segment mean
__device__ __align__(16) float g_T  [NQ * 192];           // gelu(M @ pred0 + b) fp32
__device__ int   g_start[NQ + 1];                         // segment offsets (qidx sorted)

__device__ __forceinline__ float gelu_f(float x) {
    return 0.5f * x * (1.0f + erff(x * 0.70710678118654752f));
}

#define SWZ(o) ((o) ^ (((o) >> 3) & 0x70))

__device__ __forceinline__ uint32_t smem_u32(const void* p) {
    uint32_t a;
    asm("{ .reg .u64 t; cvta.to.shared.u64 t, %1; cvt.u32.u64 %0, t; }" : "=r"(a) : "l"(p));
    return a;
}
__device__ __forceinline__ void cp_async16(uint32_t dst, const void* src, int srcsize) {
    asm volatile("cp.async.cg.shared.global [%0], [%1], 16, %2;"
                 :: "r"(dst), "l"(src), "r"(srcsize) : "memory");
}
#define CP_COMMIT()  asm volatile("cp.async.commit_group;" ::: "memory")
#define CP_WAIT0()   asm volatile("cp.async.wait_group 0;" ::: "memory")
#define LDSM_X4(r0, r1, r2, r3, addr) \
    asm volatile("ldmatrix.sync.aligned.m8n8.x4.shared.b16 {%0,%1,%2,%3}, [%4];" \
                 : "=r"(r0), "=r"(r1), "=r"(r2), "=r"(r3) : "r"(addr))
#define MMA_BF16(acc, a, b) \
    asm volatile( \
        "mma.sync.aligned.m16n8k16.row.col.f32.bf16.bf16.f32 " \
        "{%0,%1,%2,%3}, {%4,%5,%6,%7}, {%8,%9}, {%0,%1,%2,%3};" \
        : "+f"((acc)[0]), "+f"((acc)[1]), "+f"((acc)[2]), "+f"((acc)[3]) \
        : "r"((a)[0]), "r"((a)[1]), "r"((a)[2]), "r"((a)[3]), \
          "r"((b)[0]), "r"((b)[1]))

// ---------------- generic bf16 tensor-core GEMM (node layers) ----------------
template <int NT, int KT, bool GELU, bool OUT_BF16>
__global__ __launch_bounds__(256)
void bf16gemm_kernel(const bf16* __restrict__ A, const bf16* __restrict__ Bt,
                     const float* __restrict__ bias, void* __restrict__ Cv) {
    constexpr int NC = KT / 64;
    extern __shared__ __align__(128) char smem_raw[];
    uint32_t sb = (smem_u32(smem_raw) + 127u) & ~127u;

    const int tid  = threadIdx.x;
    const int lane = tid & 31;
    const int warp = tid >> 5;
    const int gid  = lane >> 2;
    const int tig  = lane & 3;
    const int wm   = (warp & 3) * 32;
    const int wn   = (warp >> 2) * 64;
    const int bm   = blockIdx.y * 128;
    const int bn   = blockIdx.x * 128;

    float acc[2][8][4];
    #pragma unroll
    for (int mf = 0; mf < 2; mf++)
        #pragma unroll
        for (int nf = 0; nf < 8; nf++)
            #pragma unroll
            for (int i = 0; i < 4; i++) acc[mf][nf][i] = 0.f;

    auto load_tile = [&](int kc, int b) {
        #pragma unroll
        for (int i = 0; i < 4; i++) {
            int fid = i * 256 + tid;
            int r = fid >> 3, c = fid & 7;
            uint32_t dst = sb + b * 16384 + SWZ(r * 128 + c * 16);
            cp_async16(dst, A + (size_t)(bm + r) * KT + kc * 64 + c * 8, 16);
        }
        #pragma unroll
        for (int i = 0; i < 4; i++) {
            int fid = i * 256 + tid;
            int r = fid >> 3, c = fid & 7;
            int n = bn + r;
            int valid = (n < NT);
            size_t nn = valid ? (size_t)n : 0;
            uint32_t dst = sb + 32768 + b * 16384 + SWZ(r * 128 + c * 16);
            cp_async16(dst, Bt + nn * KT + kc * 64 + c * 8, valid ? 16 : 0);
        }
        CP_COMMIT();
    };

    const int q  = lane >> 3;
    const int lq = lane & 7;
    const uint32_t swz = (uint32_t)lq << 4;
    const uint32_t kq  = (uint32_t)(q >> 1) << 4;
    const int mrow = (q & 1) * 8 + lq;
    uint32_t aoff[2], boff[4];
    #pragma unroll
    for (int mf = 0; mf < 2; mf++) aoff[mf] = (uint32_t)(wm + mf * 16 + mrow) << 7;
    #pragma unroll
    for (int p = 0; p < 4; p++)    boff[p]  = (uint32_t)(wn + p * 16 + mrow) << 7;

    load_tile(0, 0);
    int buf = 0;
    for (int c = 0; c < NC; c++) {
        CP_WAIT0();
        __syncthreads();
        if (c + 1 < NC) load_tile(c + 1, buf ^ 1);
        const uint32_t sA = sb + buf * 16384;
        const uint32_t sB = sb + 32768 + buf * 16384;
        #pragma unroll
        for (int ks = 0; ks < 4; ks++) {
            const uint32_t kxor = ((uint32_t)(ks * 32) + kq) ^ swz;
            uint32_t a[2][4];
            LDSM_X4(a[0][0], a[0][1], a[0][2], a[0][3], sA + aoff[0] + kxor);
            LDSM_X4(a[1][0], a[1][1], a[1][2], a[1][3], sA + aoff[1] + kxor);
            uint32_t b[8][2];
            #pragma unroll
            for (int p = 0; p < 4; p++) {
                uint32_t r0, r1, r2, r3;
                LDSM_X4(r0, r1, r2, r3, sB + boff[p] + kxor);
                b[2 * p][0] = r0; b[2 * p + 1][0] = r1;
                b[2 * p][1] = r2; b[2 * p + 1][1] = r3;
            }
            #pragma unroll
            for (int mf = 0; mf < 2; mf++)
                #pragma unroll
                for (int nf = 0; nf < 8; nf++)
                    MMA_BF16(acc[mf][nf], a[mf], b[nf]);
        }
        __syncthreads();
        buf ^= 1;
    }

    #pragma unroll
    for (int mf = 0; mf < 2; mf++) {
        int row0 = bm + wm + mf * 16 + gid;
        int row1 = row0 + 8;
        #pragma unroll
        for (int nf = 0; nf < 8; nf++) {
            int col = bn + wn + nf * 8 + tig * 2;
            if (col < NT) {
                float bb0 = bias ? bias[col]     : 0.f;
                float bb1 = bias ? bias[col + 1] : 0.f;
                float v00 = acc[mf][nf][0] + bb0;
                float v01 = acc[mf][nf][1] + bb1;
                float v10 = acc[mf][nf][2] + bb0;
                float v11 = acc[mf][nf][3] + bb1;
                if (GELU) {
                    v00 = gelu_f(v00); v01 = gelu_f(v01);
                    v10 = gelu_f(v10); v11 = gelu_f(v11);
                }
                if (OUT_BF16) {
                    bf16* C = (bf16*)Cv;
                    *(__nv_bfloat162*)&C[(size_t)row0 * NT + col] = __floats2bfloat162_rn(v00, v01);
                    *(__nv_bfloat162*)&C[(size_t)row1 * NT + col] = __floats2bfloat162_rn(v10, v11);
                } else {
                    float* C = (float*)Cv;
                    *(float2*)&C[(size_t)row0 * NT + col] = make_float2(v00, v01);
                    *(float2*)&C[(size_t)row1 * NT + col] = make_float2(v10, v11);
                }
            }
        }
    }
}

// ---------------- MEGAKERNEL: edge-gather+gelu -> msg1 -> msg2, all in smem ----------------
// Per CTA: 128 edges. H0 tile (128x384 bf16) and H1 tile (128x384 bf16) live in smem.
// Only H2 (128x192 bf16) is written to gmem.
// smem: H0s[6 chunks x 16KB) @0, H1s @98304, Bbuf(32KB) @196608. Total 229376 B.
__global__ __launch_bounds__(256, 1)
void mega_kernel(const float* __restrict__ A1, const float* __restrict__ A2,
                 const int* __restrict__ edges,
                 const bf16* __restrict__ Wt1, const float* __restrict__ b1,
                 const bf16* __restrict__ Wt2, const float* __restrict__ b2,
                 bf16* __restrict__ H2) {
    constexpr uint32_t OFF_H1 = 98304;
    constexpr uint32_t OFF_B  = 196608;
    extern __shared__ __align__(128) char smem_raw[];
    uint32_t sb = (smem_u32(smem_raw) + 127u) & ~127u;

    const int tid  = threadIdx.x;
    const int lane = tid & 31;
    const int warp = tid >> 5;
    const int gid  = lane >> 2;
    const int tig  = lane & 3;
    const int wm   = (warp & 3) * 32;
    const int bm   = blockIdx.x * 128;

    // ldmatrix lane geometry (shared by all phases)
    const int q  = lane >> 3;
    const int lq = lane & 7;
    const uint32_t swz = (uint32_t)lq << 4;
    const uint32_t kq  = (uint32_t)(q >> 1) << 4;
    const int mrow = (q & 1) * 8 + lq;
    uint32_t aoff[2];
    #pragma unroll
    for (int mf = 0; mf < 2; mf++) aoff[mf] = (uint32_t)(wm + mf * 16 + mrow) << 7;

    // ================= Phase A: gather + gelu -> H0 smem tile =================
    {
        char* smem_g = smem_raw + (sb - smem_u32(smem_raw));   // generic ptr at sb
        int* qs = (int*)(smem_g + OFF_B);
        int* gs = qs + 128;
        if (tid < 128) {
            qs[tid] = edges[2 * (bm + tid)];
            gs[tid] = edges[2 * (bm + tid) + 1];
        }
        __syncthreads();
        const int r = tid >> 1;
        const int h = tid & 1;
        const float* a1 = A1 + (size_t)gs[r] * 384 + h * 192;
        const float* a2 = A2 + (size_t)qs[r] * 384 + h * 192;
        #pragma unroll 2
        for (int j = 0; j < 24; j++) {
            float4 x0 = *(const float4*)(a1 + j * 8);
            float4 x1 = *(const float4*)(a1 + j * 8 + 4);
            float4 y0 = *(const float4*)(a2 + j * 8);
            float4 y1 = *(const float4*)(a2 + j * 8 + 4);
            __nv_bfloat162 p0 = __floats2bfloat162_rn(gelu_f(x0.x + y0.x), gelu_f(x0.y + y0.y));
            __nv_bfloat162 p1 = __floats2bfloat162_rn(gelu_f(x0.z + y0.z), gelu_f(x0.w + y0.w));
            __nv_bfloat162 p2 = __floats2bfloat162_rn(gelu_f(x1.x + y1.x), gelu_f(x1.y + y1.y));
            __nv_bfloat162 p3 = __floats2bfloat162_rn(gelu_f(x1.z + y1.z), gelu_f(x1.w + y1.w));
            int c  = h * 192 + j * 8;
            int kc = c >> 6, cc = c & 63;
            uint32_t dst = sb + kc * 16384 + SWZ(r * 128 + cc * 2);
            uint4 w = make_uint4(*(uint32_t*)&p0, *(uint32_t*)&p1, *(uint32_t*)&p2, *(uint32_t*)&p3);
            asm volatile("st.shared.v4.b32 [%0], {%1,%2,%3,%4};"
                         :: "r"(dst), "r"(w.x), "r"(w.y), "r"(w.z), "r"(w.w) : "memory");
        }
        __syncthreads();
    }

    // ================= Phase B: msg1 (H0s @ Wt1^T) -> H1 smem tile =================
    {
        const int wn = (warp >> 2) * 64;
        uint32_t boff[4];
        #pragma unroll
        for (int p = 0; p < 4; p++) boff[p] = (uint32_t)(wn + p * 16 + mrow) << 7;

        auto loadB1 = [&](int nb, int kc, int b) {
            #pragma unroll
            for (int i = 0; i < 4; i++) {
                int fid = i * 256 + tid;
                int rr = fid >> 3, cc = fid & 7;
                uint32_t dst = sb + OFF_B + b * 16384 + SWZ(rr * 128 + cc * 16);
                cp_async16(dst, Wt1 + (size_t)(nb * 128 + rr) * 384 + kc * 64 + cc * 8, 16);
            }
            CP_COMMIT();
        };

        for (int nb = 0; nb < 3; nb++) {
            float acc[2][8][4];
            #pragma unroll
            for (int mf = 0; mf < 2; mf++)
                #pragma unroll
                for (int nf = 0; nf < 8; nf++)
                    #pragma unroll
                    for (int i = 0; i < 4; i++) acc[mf][nf][i] = 0.f;

            loadB1(nb, 0, 0);
            int buf = 0;
            for (int kc = 0; kc < 6; kc++) {
                CP_WAIT0();
                __syncthreads();
                if (kc + 1 < 6) loadB1(nb, kc + 1, buf ^ 1);
                const uint32_t sA = sb + kc * 16384;
                const uint32_t sB = sb + OFF_B + buf * 16384;
                #pragma unroll
                for (int ks = 0; ks < 4; ks++) {
                    const uint32_t kxor = ((uint32_t)(ks * 32) + kq) ^ swz;
                    uint32_t a[2][4];
                    LDSM_X4(a[0][0], a[0][1], a[0][2], a[0][3], sA + aoff[0] + kxor);
                    LDSM_X4(a[1][0], a[1][1], a[1][2], a[1][3], sA + aoff[1] + kxor);
                    uint32_t b[8][2];
                    #pragma unroll
                    for (int p = 0; p < 4; p++) {
                        uint32_t r0, r1, r2, r3;
                        LDSM_X4(r0, r1, r2, r3, sB + boff[p] + kxor);
                        b[2 * p][0] = r0; b[2 * p + 1][0] = r1;
                        b[2 * p][1] = r2; b[2 * p + 1][1] = r3;
                    }
                    #pragma unroll
                    for (int mf = 0; mf < 2; mf++)
                        #pragma unroll
                        for (int nf = 0; nf < 8; nf++)
                            MMA_BF16(acc[mf][nf], a[mf], b[nf]);
                }
                __syncthreads();
                buf ^= 1;
            }

            // epilogue: gelu(acc + b1) -> H1s (swizzled chunk layout)
            #pragma unroll
            for (int mf = 0; mf < 2; mf++) {
                int row0 = wm + mf * 16 + gid;
                int row1 = row0 + 8;
                #pragma unroll
                for (int nf = 0; nf < 8; nf++) {
                    int col = nb * 128 + wn + nf * 8 + tig * 2;
                    float bb0 = b1[col], bb1 = b1[col + 1];
                    __nv_bfloat162 v0 = __floats2bfloat162_rn(gelu_f(acc[mf][nf][0] + bb0),
                                                              gelu_f(acc[mf][nf][1] + bb1));
                    __nv_bfloat162 v1 = __floats2bfloat162_rn(gelu_f(acc[mf][nf][2] + bb0),
                                                              gelu_f(acc[mf][nf][3] + bb1));
                    int kcd = col >> 6, ccd = col & 63;
                    uint32_t d0 = sb + OFF_H1 + kcd * 16384 + SWZ(row0 * 128 + ccd * 2);
                    uint32_t d1 = sb + OFF_H1 + kcd * 16384 + SWZ(row1 * 128 + ccd * 2);
                    asm volatile("st.shared.b32 [%0], %1;" :: "r"(d0), "r"(*(uint32_t*)&v0) : "memory");
                    asm volatile("st.shared.b32 [%0], %1;" :: "r"(d1), "r"(*(uint32_t*)&v1) : "memory");
                }
            }
            __syncthreads();
        }
    }

    // ================= Phase C: msg2 (H1s @ Wt2^T) -> H2 gmem =================
    {
        const int wn2 = (warp >> 2) * 96;
        uint32_t boff2[6];
        #pragma unroll
        for (int p = 0; p < 6; p++) boff2[p] = (uint32_t)(wn2 + p * 16 + mrow) << 7;

        float acc2[2][12][4];
        #pragma unroll
        for (int mf = 0; mf < 2; mf++)
            #pragma unroll
            for (int nf = 0; nf < 12; nf++)
                #pragma unroll
                for (int i = 0; i < 4; i++) acc2[mf][nf][i] = 0.f;

        for (int kc = 0; kc < 6; kc++) {
            __syncthreads();   // previous chunk compute done before overwriting Bbuf
            #pragma unroll
            for (int i = 0; i < 6; i++) {
                int fid = i * 256 + tid;        // 1536 x 16B = 24KB (192 rows)
                int rr = fid >> 3, cc = fid & 7;
                uint32_t dst = sb + OFF_B + SWZ(rr * 128 + cc * 16);
                cp_async16(dst, Wt2 + (size_t)rr * 384 + kc * 64 + cc * 8, 16);
            }
            CP_COMMIT();
            CP_WAIT0();
            __syncthreads();
            const uint32_t sA = sb + OFF_H1 + kc * 16384;
            const uint32_t sB = sb + OFF_B;
            #pragma unroll
            for (int ks = 0; ks < 4; ks++) {
                const uint32_t kxor = ((uint32_t)(ks * 32) + kq) ^ swz;
                uint32_t a[2][4];
                LDSM_X4(a[0][0], a[0][1], a[0][2], a[0][3], sA + aoff[0] + kxor);
                LDSM_X4(a[1][0], a[1][1], a[1][2], a[1][3], sA + aoff[1] + kxor);
                uint32_t b[12][2];
                #pragma unroll
                for (int p = 0; p < 6; p++) {
                    uint32_t r0, r1, r2, r3;
                    LDSM_X4(r0, r1, r2, r3, sB + boff2[p] + kxor);
                    b[2 * p][0] = r0; b[2 * p + 1][0] = r1;
                    b[2 * p][1] = r2; b[2 * p + 1][1] = r3;
                }
                #pragma unroll
                for (int mf = 0; mf < 2; mf++)
                    #pragma unroll
                    for (int nf = 0; nf < 12; nf++)
                        MMA_BF16(acc2[mf][nf], a[mf], b[nf]);
            }
        }

        // epilogue: acc2 + b2 -> H2 (bf16, gmem)
        #pragma unroll
        for (int mf = 0; mf < 2; mf++) {
            int row0 = bm + wm + mf * 16 + gid;
            int row1 = row0 + 8;
            #pragma unroll
            for (int nf = 0; nf < 12; nf++) {
                int col = wn2 + nf * 8 + tig * 2;
                float bb0 = b2[col], bb1 = b2[col + 1];
                __nv_bfloat162 v0 = __floats2bfloat162_rn(acc2[mf][nf][0] + bb0,
                                                          acc2[mf][nf][1] + bb1);
                __nv_bfloat162 v1 = __floats2bfloat162_rn(acc2[mf][nf][2] + bb0,
                                                          acc2[mf][nf][3] + bb1);
                *(__nv_bfloat162*)&H2[(size_t)row0 * 192 + col] = v0;
                *(__nv_bfloat162*)&H2[(size_t)row1 * 192 + col] = v1;
            }
        }
    }
}

// ---------------- weight prep ----------------
__global__ void fold_w_kernel(const float* __restrict__ proj_w,
                              const float* __restrict__ msg0_w) {
    int idx = blockIdx.x * blockDim.x + threadIdx.x;
    if (idx >= 192 * 384) return;
    int i = idx / 384, n = idx % 384;
    float s = 0.f;
    #pragma unroll 4
    for (int j = 0; j < 192; j++)
        s += proj_w[i * 192 + j] * msg0_w[j * 384 + n];
    g_WcT[n * 192 + i] = __float2bfloat16_rn(s);
}
__global__ void fold_b_kernel(const float* __restrict__ proj_b,
                              const float* __restrict__ msg0_w,
                              const float* __restrict__ msg0_b) {
    int n = blockIdx.x * blockDim.x + threadIdx.x;
    if (n >= 384) return;
    float s = msg0_b[n];
    #pragma unroll 4
    for (int j = 0; j < 192; j++)
        s += proj_b[j] * msg0_w[j * 384 + n];
    g_bc[n] = s;
}
__global__ void transpose_bf16_kernel(const float* __restrict__ src, bf16* __restrict__ dst,
                                      int K, int N) {
    int idx = blockIdx.x * blockDim.x + threadIdx.x;
    if (idx >= K * N) return;
    int k = idx / N, n = idx % N;
    dst[n * K + k] = __float2bfloat16_rn(src[idx]);
}
__global__ void cvt_bf16_kernel(const float* __restrict__ src, bf16* __restrict__ dst, int n4) {
    int i = blockIdx.x * blockDim.x + threadIdx.x;
    if (i >= n4) return;
    float4 v = *(const float4*)(src + i * 4);
    __nv_bfloat162 p0 = __floats2bfloat162_rn(v.x, v.y);
    __nv_bfloat162 p1 = __floats2bfloat162_rn(v.z, v.w);
    *(uint2*)(dst + i * 4) = make_uint2(*(uint32_t*)&p0, *(uint32_t*)&p1);
}

// ---------------- sincos positional embedding (bf16 out) ----------------
__global__ void qe_kernel(const float* __restrict__ query_pos) {
    int idx = blockIdx.x * blockDim.x + threadIdx.x;
    if (idx >= NQ * 192) return;
    int qq = idx / 192, c = idx % 192;
    int d = c / 64, j = c % 64;
    int i = (j < 32) ? j : j - 32;
    float coord = query_pos[qq * 3 + d];
    float expo  = (2.0f * (float)i) / 64.0f;
    float omega = powf(10000.0f, -expo);
    float a = coord * omega;
    g_QEh[idx] = __float2bfloat16_rn((j < 32) ? sinf(a) : cosf(a));
}

// ---------------- segment offsets (qidx sorted ascending) ----------------
__global__ void segstart_kernel(const int* __restrict__ edges) {
    int q = blockIdx.x * blockDim.x + threadIdx.x;
    if (q > NQ) return;
    if (q == NQ) { g_start[NQ] = NE; return; }
    int lo = 0, hi = NE;
    while (lo < hi) {
        int mid = (lo + hi) >> 1;
        int v = edges[2 * mid];
        if (v < q) lo = mid + 1; else hi = mid;
    }
    g_start[q] = lo;
}

// ---------------- segment mean over H2 (bf16) -> M bf16 ----------------
__global__ void segmean_kernel(const bf16* __restrict__ H2) {
    int q = blockIdx.x;
    int c = threadIdx.x;   // 0..191
    int s = g_start[q], e = g_start[q + 1];
    float sum = 0.f;
    for (int i = s; i < e; i++)
        sum += __bfloat162float(H2[(size_t)i * 192 + c]);
    float cnt = (float)(e - s);
    g_Mh[q * 192 + c] = __float2bfloat16_rn(sum / fmaxf(cnt, 1.0f));
}

// ---------------- final tiny projection ----------------
__global__ void outk_kernel(const float* __restrict__ pred1_w,
                            const float* __restrict__ pred1_b,
                            float* __restrict__ out) {
    int idx = blockIdx.x * blockDim.x + threadIdx.x;
    if (idx >= NQ * 4) return;
    int q = idx / 4, o = idx % 4;
    float s = pred1_b[o];
    #pragma unroll 4
    for (int k = 0; k < 192; k++)
        s += g_T[q * 192 + k] * pred1_w[k * 4 + o];
    out[idx] = s;
}

// ---------------- launch ----------------
static const int GEMM_SMEM = 65536 + 128;
static const int MEGA_SMEM = 98304 * 2 + 32768 + 256;   // 229632

extern "C" void kernel_launch(void* const* d_in, const int* in_sizes, int n_in,
                              void* d_out, int out_size) {
    const float* x        = (const float*)d_in[0];
    const float* qpos     = (const float*)d_in[1];
    const int*   edges    = (const int*)d_in[2];    // int32 (JAX x64 disabled)
    const float* proj_w   = (const float*)d_in[3];
    const float* proj_b   = (const float*)d_in[4];
    const float* msg0_w   = (const float*)d_in[5];
    const float* msg0_b   = (const float*)d_in[6];
    const float* msg1_w   = (const float*)d_in[7];
    const float* msg1_b   = (const float*)d_in[8];
    const float* msg2_w   = (const float*)d_in[9];
    const float* msg2_b   = (const float*)d_in[10];
    const float* pred0_w  = (const float*)d_in[11];
    const float* pred0_b  = (const float*)d_in[12];
    const float* pred1_w  = (const float*)d_in[13];
    const float* pred1_b  = (const float*)d_in[14];
    float*       out      = (float*)d_out;

    bf16 *pWcT, *pWbT, *pWt1, *pWt2, *pWp0T, *pXh, *pQEh, *pH2h, *pMh;
    float *pbc, *pA1, *pA2, *pT;
    cudaGetSymbolAddress((void**)&pWcT,  g_WcT);
    cudaGetSymbolAddress((void**)&pWbT,  g_WbT);
    cudaGetSymbolAddress((void**)&pWt1,  g_Wt1);
    cudaGetSymbolAddress((void**)&pWt2,  g_Wt2);
    cudaGetSymbolAddress((void**)&pWp0T, g_Wp0T);
    cudaGetSymbolAddress((void**)&pbc,   g_bc);
    cudaGetSymbolAddress((void**)&pXh,   g_Xh);
    cudaGetSymbolAddress((void**)&pQEh,  g_QEh);
    cudaGetSymbolAddress((void**)&pA1,   g_A1);
    cudaGetSymbolAddress((void**)&pA2,   g_A2);
    cudaGetSymbolAddress((void**)&pH2h,  g_H2h);
    cudaGetSymbolAddress((void**)&pMh,   g_Mh);
    cudaGetSymbolAddress((void**)&pT,    g_T);

    cudaFuncSetAttribute(bf16gemm_kernel<384,192,false,false>, cudaFuncAttributeMaxDynamicSharedMemorySize, GEMM_SMEM);
    cudaFuncSetAttribute(bf16gemm_kernel<192,192,true, false>, cudaFuncAttributeMaxDynamicSharedMemorySize, GEMM_SMEM);
    cudaFuncSetAttribute(mega_kernel, cudaFuncAttributeMaxDynamicSharedMemorySize, MEGA_SMEM);

    // 1) weight prep
    fold_w_kernel<<<(192 * 384 + 255) / 256, 256>>>(proj_w, msg0_w);
    fold_b_kernel<<<2, 192>>>(proj_b, msg0_w, msg0_b);
    transpose_bf16_kernel<<<(192 * 384 + 255) / 256, 256>>>(msg0_w + 192 * 384, pWbT, 192, 384);
    transpose_bf16_kernel<<<(384 * 384 + 255) / 256, 256>>>(msg1_w, pWt1, 384, 384);
    transpose_bf16_kernel<<<(384 * 192 + 255) / 256, 256>>>(msg2_w, pWt2, 384, 192);
    transpose_bf16_kernel<<<(192 * 192 + 255) / 256, 256>>>(pred0_w, pWp0T, 192, 192);

    // 2) input conversions
    cvt_bf16_kernel<<<(S * 192 / 4 + 255) / 256, 256>>>(x, pXh, S * 192 / 4);
    qe_kernel<<<(NQ * 192 + 255) / 256, 256>>>(qpos);

    // 3) A1 = x @ Wc + bc   [S, 384] fp32
    bf16gemm_kernel<384,192,false,false><<<dim3(3, S / 128), 256, GEMM_SMEM>>>(pXh, pWcT, pbc, pA1);

    // 4) A2 = QE @ msg0_w_bot   [NQ, 384] fp32
    bf16gemm_kernel<384,192,false,false><<<dim3(3, NQ / 128), 256, GEMM_SMEM>>>(pQEh, pWbT, nullptr, pA2);

    // 5) segment offsets (independent; overlap with mega)
    segstart_kernel<<<(NQ + 1 + 255) / 256, 256>>>(edges);

    // 6) MEGA: edge gather+gelu -> msg1 -> msg2 -> H2 bf16
    mega_kernel<<<NE / 128, 256, MEGA_SMEM>>>(pA1, pA2, edges, pWt1, msg1_b, pWt2, msg2_b, pH2h);

    // 7) segment mean -> M bf16
    segmean_kernel<<<NQ, 192>>>(pH2h);

    // 8) T = gelu(M @ pred0_w + pred0_b)  [NQ, 192] fp32
    bf16gemm_kernel<192,192,true,false><<<dim3(2, NQ / 128), 256, GEMM_SMEM>>>(pMh, pWp0T, pred0_b, pT);

    // 9) out = T @ pred1_w + pred1_b  [NQ, 4]
    outk_kernel<<<(NQ * 4 + 127) / 128, 128>>>(pred1_w, pred1_b, out);
}

// round 9
// speedup vs baseline: 1.2272x; 1.2272x over previous
#include <cuda_runtime.h>
#include <cuda_bf16.h>
#include <math.h>
#include <stdint.h>

// ---------------- problem constants ----------------
#define NQ   32768
#define NE   262144
#define S    32768

typedef __nv_bfloat16 bf16;

// ---------------- scratch (device globals) ----------------
__device__ __align__(16) bf16  g_WcT [384 * 192];         // (proj_w @ msg0_w_top)^T [n][k]
__device__ __align__(16) bf16  g_WbT [384 * 192];         // msg0_w_bot^T
__device__ __align__(16) bf16  g_Wt1 [384 * 384];         // msg1_w^T
__device__ __align__(16) bf16  g_Wt2 [192 * 384];         // msg2_w^T
__device__ __align__(16) bf16  g_Wp0T[192 * 192];         // pred0_w^T
__device__ __align__(16) float g_bc[384];                 // folded bias
__device__ __align__(16) bf16  g_Xh [S * 192];            // x in bf16
__device__ __align__(16) bf16  g_QEh[NQ * 192];           // sincos embed bf16
__device__ __align__(16) float g_A1[S * 384];             // x @ Wc + bc (fp32)
__device__ __align__(16) float g_A2[NQ * 384];            // QE @ msg0_w_bot (fp32)
__device__ __align__(16) bf16  g_H0h[(size_t)NE * 384];   // gelu(A1[g]+A2[q]); reused for H2
__device__ __align__(16) bf16  g_H1h[(size_t)NE * 384];   // gelu(H0 @ msg1 + b1)
__device__ __align__(16) bf16  g_Mh [NQ * 192];           // segment mean
__device__ __align__(16) float g_T  [NQ * 192];           // gelu(M @ pred0 + b) fp32
__device__ int   g_start[NQ + 1];                         // segment offsets (qidx sorted)

__device__ __forceinline__ float gelu_f(float x) {
    return 0.5f * x * (1.0f + erff(x * 0.70710678118654752f));
}

#define SWZ(o) ((o) ^ (((o) >> 3) & 0x70))

__device__ __forceinline__ uint32_t smem_u32(const void* p) {
    uint32_t a;
    asm("{ .reg .u64 t; cvta.to.shared.u64 t, %1; cvt.u32.u64 %0, t; }" : "=r"(a) : "l"(p));
    return a;
}
__device__ __forceinline__ void cp_async16(uint32_t dst, const void* src) {
    asm volatile("cp.async.cg.shared.global [%0], [%1], 16;"
                 :: "r"(dst), "l"(src) : "memory");
}
#define CP_COMMIT()  asm volatile("cp.async.commit_group;" ::: "memory")
#define CP_WAIT_1()  asm volatile("cp.async.wait_group 1;" ::: "memory")
#define CP_WAIT_0()  asm volatile("cp.async.wait_group 0;" ::: "memory")
#define LDSM_X4(r0, r1, r2, r3, addr) \
    asm volatile("ldmatrix.sync.aligned.m8n8.x4.shared.b16 {%0,%1,%2,%3}, [%4];" \
                 : "=r"(r0), "=r"(r1), "=r"(r2), "=r"(r3) : "r"(addr))
#define MMA_BF16(acc, a, b) \
    asm volatile( \
        "mma.sync.aligned.m16n8k16.row.col.f32.bf16.bf16.f32 " \
        "{%0,%1,%2,%3}, {%4,%5,%6,%7}, {%8,%9}, {%0,%1,%2,%3};" \
        : "+f"((acc)[0]), "+f"((acc)[1]), "+f"((acc)[2]), "+f"((acc)[3]) \
        : "r"((a)[0]), "r"((a)[1]), "r"((a)[2]), "r"((a)[3]), \
          "r"((b)[0]), "r"((b)[1]))

// ---------------- bf16 tensor-core GEMM, 3-stage cp.async pipeline ----------------
// C[M, NT] = op(A[M, KT] @ Bt^T + bias). A bf16 row-major [M][KT], Bt bf16 [NT][KT].
// CTA tile 128 x BN (BN in {128, 96}); NT % BN == 0 (no bounds checks).
// BN=128: 8 warps 4Mx2N, warp 32x64.  BN=96: 8 warps 4Mx2N, warp 32x48.
template <int NT, int KT, int BN, bool GELU, bool OUT_BF16>
__global__ __launch_bounds__(256, 2)
void bf16gemm_kernel(const bf16* __restrict__ A, const bf16* __restrict__ Bt,
                     const float* __restrict__ bias, void* __restrict__ Cv) {
    constexpr int NC    = KT / 64;           // k-tiles
    constexpr int ASZ   = 16384;             // A stage bytes (128 x 64 bf16)
    constexpr int BSZ   = BN * 128;          // B stage bytes
    constexpr int NFRAG = BN / 16;           // 8 or 6 n-frags per warp
    constexpr int PQ    = NFRAG / 2;         // ldmatrix quads: 4 or 3
    constexpr int BITER = BN / 32;           // B loader iters: 4 or 3

    extern __shared__ __align__(128) char smem_raw[];
    uint32_t sb = (smem_u32(smem_raw) + 127u) & ~127u;

    const int tid  = threadIdx.x;
    const int lane = tid & 31;
    const int warp = tid >> 5;
    const int gid  = lane >> 2;
    const int tig  = lane & 3;
    const int wm   = (warp & 3) * 32;
    const int wn   = (warp >> 2) * (BN / 2);
    const int bm   = blockIdx.y * 128;
    const int bn   = blockIdx.x * BN;

    float acc[2][NFRAG][4];
    #pragma unroll
    for (int mf = 0; mf < 2; mf++)
        #pragma unroll
        for (int nf = 0; nf < NFRAG; nf++)
            #pragma unroll
            for (int i = 0; i < 4; i++) acc[mf][nf][i] = 0.f;

    auto load_tile = [&](int kc, int s) {
        #pragma unroll
        for (int i = 0; i < 4; i++) {
            int fid = i * 256 + tid;
            int r = fid >> 3, c = fid & 7;
            uint32_t dst = sb + s * ASZ + SWZ(r * 128 + c * 16);
            cp_async16(dst, A + (size_t)(bm + r) * KT + kc * 64 + c * 8);
        }
        #pragma unroll
        for (int i = 0; i < BITER; i++) {
            int fid = i * 256 + tid;
            int r = fid >> 3, c = fid & 7;
            uint32_t dst = sb + 3 * ASZ + s * BSZ + SWZ(r * 128 + c * 16);
            cp_async16(dst, Bt + (size_t)(bn + r) * KT + kc * 64 + c * 8);
        }
        CP_COMMIT();
    };

    const int q  = lane >> 3;
    const int lq = lane & 7;
    const uint32_t swz = (uint32_t)lq << 4;
    const uint32_t kq  = (uint32_t)(q >> 1) << 4;
    const int mrow = (q & 1) * 8 + lq;
    uint32_t aoff[2], boff[PQ];
    #pragma unroll
    for (int mf = 0; mf < 2; mf++) aoff[mf] = (uint32_t)(wm + mf * 16 + mrow) << 7;
    #pragma unroll
    for (int p = 0; p < PQ; p++)   boff[p]  = (uint32_t)(wn + p * 16 + mrow) << 7;

    load_tile(0, 0);
    if (NC > 1) load_tile(1, 1);
    for (int c = 0; c < NC; c++) {
        if (c < NC - 1) { CP_WAIT_1(); } else { CP_WAIT_0(); }
        __syncthreads();
        if (c + 2 < NC) load_tile(c + 2, (c + 2) % 3);

        const uint32_t sA = sb + (c % 3) * ASZ;
        const uint32_t sB = sb + 3 * ASZ + (c % 3) * BSZ;
        #pragma unroll
        for (int ks = 0; ks < 4; ks++) {
            const uint32_t kxor = ((uint32_t)(ks * 32) + kq) ^ swz;
            uint32_t a[2][4];
            LDSM_X4(a[0][0], a[0][1], a[0][2], a[0][3], sA + aoff[0] + kxor);
            LDSM_X4(a[1][0], a[1][1], a[1][2], a[1][3], sA + aoff[1] + kxor);
            uint32_t b[NFRAG][2];
            #pragma unroll
            for (int p = 0; p < PQ; p++) {
                uint32_t r0, r1, r2, r3;
                LDSM_X4(r0, r1, r2, r3, sB + boff[p] + kxor);
                b[2 * p][0] = r0; b[2 * p + 1][0] = r1;
                b[2 * p][1] = r2; b[2 * p + 1][1] = r3;
            }
            #pragma unroll
            for (int mf = 0; mf < 2; mf++)
                #pragma unroll
                for (int nf = 0; nf < NFRAG; nf++)
                    MMA_BF16(acc[mf][nf], a[mf], b[nf]);
        }
        __syncthreads();
    }

    // ---- epilogue: direct register -> gmem ----
    #pragma unroll
    for (int mf = 0; mf < 2; mf++) {
        int row0 = bm + wm + mf * 16 + gid;
        int row1 = row0 + 8;
        #pragma unroll
        for (int nf = 0; nf < NFRAG; nf++) {
            int col = bn + wn + nf * 8 + tig * 2;
            float bb0 = bias ? bias[col]     : 0.f;
            float bb1 = bias ? bias[col + 1] : 0.f;
            float v00 = acc[mf][nf][0] + bb0;
            float v01 = acc[mf][nf][1] + bb1;
            float v10 = acc[mf][nf][2] + bb0;
            float v11 = acc[mf][nf][3] + bb1;
            if (GELU) {
                v00 = gelu_f(v00); v01 = gelu_f(v01);
                v10 = gelu_f(v10); v11 = gelu_f(v11);
            }
            if (OUT_BF16) {
                bf16* C = (bf16*)Cv;
                *(__nv_bfloat162*)&C[(size_t)row0 * NT + col] = __floats2bfloat162_rn(v00, v01);
                *(__nv_bfloat162*)&C[(size_t)row1 * NT + col] = __floats2bfloat162_rn(v10, v11);
            } else {
                float* C = (float*)Cv;
                *(float2*)&C[(size_t)row0 * NT + col] = make_float2(v00, v01);
                *(float2*)&C[(size_t)row1 * NT + col] = make_float2(v10, v11);
            }
        }
    }
}

// ---------------- weight prep ----------------
__global__ void fold_w_kernel(const float* __restrict__ proj_w,
                              const float* __restrict__ msg0_w) {
    int idx = blockIdx.x * blockDim.x + threadIdx.x;
    if (idx >= 192 * 384) return;
    int i = idx / 384, n = idx % 384;
    float s = 0.f;
    #pragma unroll 4
    for (int j = 0; j < 192; j++)
        s += proj_w[i * 192 + j] * msg0_w[j * 384 + n];
    g_WcT[n * 192 + i] = __float2bfloat16_rn(s);
}
__global__ void fold_b_kernel(const float* __restrict__ proj_b,
                              const float* __restrict__ msg0_w,
                              const float* __restrict__ msg0_b) {
    int n = blockIdx.x * blockDim.x + threadIdx.x;
    if (n >= 384) return;
    float s = msg0_b[n];
    #pragma unroll 4
    for (int j = 0; j < 192; j++)
        s += proj_b[j] * msg0_w[j * 384 + n];
    g_bc[n] = s;
}
__global__ void transpose_bf16_kernel(const float* __restrict__ src, bf16* __restrict__ dst,
                                      int K, int N) {
    int idx = blockIdx.x * blockDim.x + threadIdx.x;
    if (idx >= K * N) return;
    int k = idx / N, n = idx % N;
    dst[n * K + k] = __float2bfloat16_rn(src[idx]);
}
__global__ void cvt_bf16_kernel(const float* __restrict__ src, bf16* __restrict__ dst, int n4) {
    int i = blockIdx.x * blockDim.x + threadIdx.x;
    if (i >= n4) return;
    float4 v = *(const float4*)(src + i * 4);
    __nv_bfloat162 p0 = __floats2bfloat162_rn(v.x, v.y);
    __nv_bfloat162 p1 = __floats2bfloat162_rn(v.z, v.w);
    *(uint2*)(dst + i * 4) = make_uint2(*(uint32_t*)&p0, *(uint32_t*)&p1);
}

// ---------------- sincos positional embedding (bf16 out) ----------------
__global__ void qe_kernel(const float* __restrict__ query_pos) {
    int idx = blockIdx.x * blockDim.x + threadIdx.x;
    if (idx >= NQ * 192) return;
    int qq = idx / 192, c = idx % 192;
    int d = c / 64, j = c % 64;
    int i = (j < 32) ? j : j - 32;
    float coord = query_pos[qq * 3 + d];
    float expo  = (2.0f * (float)i) / 64.0f;
    float omega = powf(10000.0f, -expo);
    float a = coord * omega;
    g_QEh[idx] = __float2bfloat16_rn((j < 32) ? sinf(a) : cosf(a));
}

// ---------------- edge layer 0: H0[e] = bf16(gelu(A1[g]+A2[q])) ----------------
__global__ void edge0_kernel(const int* __restrict__ edges) {
    int idx = blockIdx.x * blockDim.x + threadIdx.x;   // over NE*48 (8 elems each)
    if (idx >= NE * 48) return;
    int e = idx / 48, c8 = idx % 48;
    int qi = __ldg(&edges[2 * e]);
    int gi = __ldg(&edges[2 * e + 1]);
    const float* a = &g_A1[(size_t)gi * 384 + c8 * 8];
    const float* b = &g_A2[(size_t)qi * 384 + c8 * 8];
    float4 a0 = *(const float4*)(a), a1 = *(const float4*)(a + 4);
    float4 b0 = *(const float4*)(b), b1 = *(const float4*)(b + 4);
    __nv_bfloat162 p0 = __floats2bfloat162_rn(gelu_f(a0.x + b0.x), gelu_f(a0.y + b0.y));
    __nv_bfloat162 p1 = __floats2bfloat162_rn(gelu_f(a0.z + b0.z), gelu_f(a0.w + b0.w));
    __nv_bfloat162 p2 = __floats2bfloat162_rn(gelu_f(a1.x + b1.x), gelu_f(a1.y + b1.y));
    __nv_bfloat162 p3 = __floats2bfloat162_rn(gelu_f(a1.z + b1.z), gelu_f(a1.w + b1.w));
    *(uint4*)&g_H0h[(size_t)e * 384 + c8 * 8] =
        make_uint4(*(uint32_t*)&p0, *(uint32_t*)&p1, *(uint32_t*)&p2, *(uint32_t*)&p3);
}

// ---------------- segment offsets (qidx sorted ascending) ----------------
__global__ void segstart_kernel(const int* __restrict__ edges) {
    int q = blockIdx.x * blockDim.x + threadIdx.x;
    if (q > NQ) return;
    if (q == NQ) { g_start[NQ] = NE; return; }
    int lo = 0, hi = NE;
    while (lo < hi) {
        int mid = (lo + hi) >> 1;
        int v = edges[2 * mid];
        if (v < q) lo = mid + 1; else hi = mid;
    }
    g_start[q] = lo;
}

// ---------------- segment mean over H2 (bf16) -> M bf16 ----------------
__global__ void segmean_kernel(const bf16* __restrict__ H2) {
    int q = blockIdx.x;
    int c = threadIdx.x;   // 0..191
    int s = g_start[q], e = g_start[q + 1];
    float sum = 0.f;
    for (int i = s; i < e; i++)
        sum += __bfloat162float(H2[(size_t)i * 192 + c]);
    float cnt = (float)(e - s);
    g_Mh[q * 192 + c] = __float2bfloat16_rn(sum / fmaxf(cnt, 1.0f));
}

// ---------------- final tiny projection ----------------
__global__ void outk_kernel(const float* __restrict__ pred1_w,
                            const float* __restrict__ pred1_b,
                            float* __restrict__ out) {
    int idx = blockIdx.x * blockDim.x + threadIdx.x;
    if (idx >= NQ * 4) return;
    int q = idx / 4, o = idx % 4;
    float s = pred1_b[o];
    #pragma unroll 4
    for (int k = 0; k < 192; k++)
        s += g_T[q * 192 + k] * pred1_w[k * 4 + o];
    out[idx] = s;
}

// ---------------- launch ----------------
static const int SMEM_BN128 = 3 * (16384 + 128 * 128) + 128;  // 98432
static const int SMEM_BN96  = 3 * (16384 +  96 * 128) + 128;  // 86144

extern "C" void kernel_launch(void* const* d_in, const int* in_sizes, int n_in,
                              void* d_out, int out_size) {
    const float* x        = (const float*)d_in[0];
    const float* qpos     = (const float*)d_in[1];
    const int*   edges    = (const int*)d_in[2];    // int32 (JAX x64 disabled)
    const float* proj_w   = (const float*)d_in[3];
    const float* proj_b   = (const float*)d_in[4];
    const float* msg0_w   = (const float*)d_in[5];
    const float* msg0_b   = (const float*)d_in[6];
    const float* msg1_w   = (const float*)d_in[7];
    const float* msg1_b   = (const float*)d_in[8];
    const float* msg2_w   = (const float*)d_in[9];
    const float* msg2_b   = (const float*)d_in[10];
    const float* pred0_w  = (const float*)d_in[11];
    const float* pred0_b  = (const float*)d_in[12];
    const float* pred1_w  = (const float*)d_in[13];
    const float* pred1_b  = (const float*)d_in[14];
    float*       out      = (float*)d_out;

    bf16 *pWcT, *pWbT, *pWt1, *pWt2, *pWp0T, *pXh, *pQEh, *pH0h, *pH1h, *pMh;
    float *pbc, *pA1, *pA2, *pT;
    cudaGetSymbolAddress((void**)&pWcT,  g_WcT);
    cudaGetSymbolAddress((void**)&pWbT,  g_WbT);
    cudaGetSymbolAddress((void**)&pWt1,  g_Wt1);
    cudaGetSymbolAddress((void**)&pWt2,  g_Wt2);
    cudaGetSymbolAddress((void**)&pWp0T, g_Wp0T);
    cudaGetSymbolAddress((void**)&pbc,   g_bc);
    cudaGetSymbolAddress((void**)&pXh,   g_Xh);
    cudaGetSymbolAddress((void**)&pQEh,  g_QEh);
    cudaGetSymbolAddress((void**)&pA1,   g_A1);
    cudaGetSymbolAddress((void**)&pA2,   g_A2);
    cudaGetSymbolAddress((void**)&pH0h,  g_H0h);
    cudaGetSymbolAddress((void**)&pH1h,  g_H1h);
    cudaGetSymbolAddress((void**)&pMh,   g_Mh);
    cudaGetSymbolAddress((void**)&pT,    g_T);
    bf16* pH2h = pH0h;   // H0 dead after msg1 GEMM; reuse for H2 (NE x 192 bf16)

    cudaFuncSetAttribute(bf16gemm_kernel<384,192,128,false,false>, cudaFuncAttributeMaxDynamicSharedMemorySize, SMEM_BN128);
    cudaFuncSetAttribute(bf16gemm_kernel<384,384,128,true, true >, cudaFuncAttributeMaxDynamicSharedMemorySize, SMEM_BN128);
    cudaFuncSetAttribute(bf16gemm_kernel<192,384, 96,false,true >, cudaFuncAttributeMaxDynamicSharedMemorySize, SMEM_BN96);
    cudaFuncSetAttribute(bf16gemm_kernel<192,192, 96,true, false>, cudaFuncAttributeMaxDynamicSharedMemorySize, SMEM_BN96);

    // 1) weight prep
    fold_w_kernel<<<(192 * 384 + 255) / 256, 256>>>(proj_w, msg0_w);
    fold_b_kernel<<<2, 192>>>(proj_b, msg0_w, msg0_b);
    transpose_bf16_kernel<<<(192 * 384 + 255) / 256, 256>>>(msg0_w + 192 * 384, pWbT, 192, 384);
    transpose_bf16_kernel<<<(384 * 384 + 255) / 256, 256>>>(msg1_w, pWt1, 384, 384);
    transpose_bf16_kernel<<<(384 * 192 + 255) / 256, 256>>>(msg2_w, pWt2, 384, 192);
    transpose_bf16_kernel<<<(192 * 192 + 255) / 256, 256>>>(pred0_w, pWp0T, 192, 192);

    // 2) input conversions
    cvt_bf16_kernel<<<(S * 192 / 4 + 255) / 256, 256>>>(x, pXh, S * 192 / 4);
    qe_kernel<<<(NQ * 192 + 255) / 256, 256>>>(qpos);

    // 3) A1 = x @ Wc + bc   [S, 384] fp32
    bf16gemm_kernel<384,192,128,false,false><<<dim3(3, S / 128), 256, SMEM_BN128>>>(pXh, pWcT, pbc, pA1);

    // 4) A2 = QE @ msg0_w_bot   [NQ, 384] fp32
    bf16gemm_kernel<384,192,128,false,false><<<dim3(3, NQ / 128), 256, SMEM_BN128>>>(pQEh, pWbT, nullptr, pA2);

    // 5) H0 = bf16(gelu(A1[g] + A2[q]))  [NE, 384]
    edge0_kernel<<<(NE * 48 + 255) / 256, 256>>>(edges);

    // 6) H1 = bf16(gelu(H0 @ msg1_w + b1))  [NE, 384]
    bf16gemm_kernel<384,384,128,true,true><<<dim3(3, NE / 128), 256, SMEM_BN128>>>(pH0h, pWt1, msg1_b, pH1h);

    // 7) H2 = bf16(H1 @ msg2_w + b2)  [NE, 192]  (into reused H0 buffer; BN=96, no waste)
    bf16gemm_kernel<192,384,96,false,true><<<dim3(2, NE / 128), 256, SMEM_BN96>>>(pH1h, pWt2, msg2_b, pH2h);

    // 8) segment offsets + mean -> M bf16
    segstart_kernel<<<(NQ + 1 + 255) / 256, 256>>>(edges);
    segmean_kernel<<<NQ, 192>>>(pH2h);

    // 9) T = gelu(M @ pred0_w + pred0_b)  [NQ, 192] fp32  (BN=96, no waste)
    bf16gemm_kernel<192,192,96,true,false><<<dim3(2, NQ / 128), 256, SMEM_BN96>>>(pMh, pWp0T, pred0_b, pT);

    // 10) out = T @ pred1_w + pred1_b  [NQ, 4]
    outk_kernel<<<(NQ * 4 + 127) / 128, 128>>>(pred1_w, pred1_b, out);
}